// round 2
// baseline (speedup 1.0000x reference)
#include <cuda_runtime.h>

// SparseMCFModel: decoder softmax w = seg_softmax(pred_w[edge_row], edge_row)
// has identical logits inside each segment (logit depends only on the segment
// key), so w[e] == 1/out_degree(edge_row[e]) EXACTLY (exp(0)=1 bitwise,
// deg < 2^24 exact in fp32). The whole GAT/GRU/decoder is dead code w.r.t.
// the output. Remaining computation, in node space:
//   x_1 = relu(demands);  x_{t+1}[n] = d_pos[n] + sum_{col(e)=n} w[e]*x_t[row(e)]
//   flow[e] = w[e] * x_10[row(e)]
//
// This version runs the ENTIRE solve in one persistent cooperative kernel:
// edge indices + weights live in registers, node state (3 x 80KB) stays hot
// in L2, iterations are separated by a software grid barrier.

#define N_NODES 20000
#define N_EDGES 200000
#define BS      256
#define MAXK    4     // max edges per thread

__device__ float g_dpos[N_NODES];
__device__ float g_x[3][N_NODES];
__device__ int   g_deg[N_NODES];

// ---- software grid barrier (requires cooperative launch for residency) ----
__device__ unsigned int g_count = 0;
__device__ unsigned int g_gen   = 0;

__device__ __forceinline__ void grid_sync(unsigned int nblocks) {
    __syncthreads();
    if (threadIdx.x == 0) {
        __threadfence();                                  // publish my block's writes
        unsigned int my = atomicAdd(&g_gen, 0u);          // read generation (pre-arrival)
        unsigned int arrived = atomicAdd(&g_count, 1u);
        if (arrived == nblocks - 1u) {
            g_count = 0u;                                 // safe: all arrived, none read
            __threadfence();                              // count reset before release
            atomicAdd(&g_gen, 1u);                        // release
        } else {
            while (atomicAdd(&g_gen, 0u) == my) { __nanosleep(64); }
        }
        __threadfence();                                  // acquire other blocks' writes
    }
    __syncthreads();
}

// ---------------- persistent cooperative solver ----------------
__global__ void __launch_bounds__(BS)
k_solve(const float* __restrict__ demands, const int* __restrict__ row,
        const int* __restrict__ col, float* __restrict__ out) {
    const unsigned int nb = gridDim.x;
    const int tid = blockIdx.x * BS + threadIdx.x;
    const int T   = (int)nb * BS;

    // --- load my edges into registers (once) ---
    int   r[MAXK], c[MAXK];
    float w[MAXK];
    bool  v[MAXK];
#pragma unroll
    for (int k = 0; k < MAXK; k++) {
        int e = tid + k * T;
        v[k] = (e < N_EDGES);
        r[k] = v[k] ? __ldg(&row[e]) : 0;
        c[k] = v[k] ? __ldg(&col[e]) : 0;
    }

    // --- node init: d_pos, x0=x1=d_pos, deg=0 ---
    for (int i = tid; i < N_NODES; i += T) {
        float d = __ldg(&demands[i]);
        d = d > 0.0f ? d : 0.0f;
        g_dpos[i]  = d;
        g_x[0][i]  = d;   // x_1
        g_x[1][i]  = d;   // pre-reset target of first update
        g_deg[i]   = 0;
    }
    grid_sync(nb);

    // --- out-degree ---
#pragma unroll
    for (int k = 0; k < MAXK; k++)
        if (v[k]) atomicAdd(&g_deg[r[k]], 1);
    grid_sync(nb);

    // --- per-edge weight into registers ---
#pragma unroll
    for (int k = 0; k < MAXK; k++)
        w[k] = v[k] ? (1.0f / (float)g_deg[r[k]]) : 0.0f;

    // --- 9 node-state updates: x_1 -> x_10 (3-buffer rotation) ---
    int cur = 0;
    for (int t = 0; t < 9; t++) {
        int nxt = cur + 1; if (nxt == 3) nxt = 0;
        int rst = nxt + 1; if (rst == 3) rst = 0;
#pragma unroll
        for (int k = 0; k < MAXK; k++)
            if (v[k]) atomicAdd(&g_x[nxt][c[k]], w[k] * g_x[cur][r[k]]);
        for (int i = tid; i < N_NODES; i += T)
            g_x[rst][i] = g_dpos[i];           // prep buffer for iter t+2
        grid_sync(nb);
        cur = nxt;
    }

    // --- flow = w * x_10[row] ---
#pragma unroll
    for (int k = 0; k < MAXK; k++)
        if (v[k]) out[tid + k * T] = w[k] * g_x[cur][r[k]];
}

// ---------------- fallback multi-launch path (proven correct) ----------------
__global__ void k_init(const float* __restrict__ demands) {
    int i = blockIdx.x * blockDim.x + threadIdx.x;
    if (i < N_NODES) {
        float d = demands[i];
        d = d > 0.0f ? d : 0.0f;
        g_dpos[i] = d; g_x[0][i] = d; g_x[1][i] = d; g_deg[i] = 0;
    }
}
__global__ void k_deg(const int* __restrict__ row) {
    int e = blockIdx.x * blockDim.x + threadIdx.x;
    if (e < N_EDGES) atomicAdd(&g_deg[row[e]], 1);
}
__global__ void k_update(const int* __restrict__ row, const int* __restrict__ col,
                         int cur, int nxt, int rst) {
    int i = blockIdx.x * blockDim.x + threadIdx.x;
    if (i < N_EDGES) {
        int rr = __ldg(&row[i]);
        float ww = 1.0f / (float)g_deg[rr];
        atomicAdd(&g_x[nxt][__ldg(&col[i])], ww * g_x[cur][rr]);
    }
    if (i < N_NODES) g_x[rst][i] = g_dpos[i];
}
__global__ void k_final(const int* __restrict__ row, float* __restrict__ out, int cur) {
    int e = blockIdx.x * blockDim.x + threadIdx.x;
    if (e < N_EDGES) {
        int rr = __ldg(&row[e]);
        out[e] = (1.0f / (float)g_deg[rr]) * g_x[cur][rr];
    }
}

extern "C" void kernel_launch(void* const* d_in, const int* in_sizes, int n_in,
                              void* d_out, int out_size) {
    const float* demands = (const float*)d_in[1];
    const int*   erow    = (const int*)d_in[2];
    const int*   ecol    = (const int*)d_in[3];
    float*       out     = (float*)d_out;

    // ---- size the cooperative grid ----
    static int coop_grid = -2;   // -2 = not probed; -1 = unsupported
    if (coop_grid == -2) {
        int dev = 0, nsm = 0, coop = 0, bpsm = 0;
        cudaGetDevice(&dev);
        cudaDeviceGetAttribute(&nsm,  cudaDevAttrMultiProcessorCount, dev);
        cudaDeviceGetAttribute(&coop, cudaDevAttrCooperativeLaunch,   dev);
        cudaOccupancyMaxActiveBlocksPerMultiprocessor(&bpsm, k_solve, BS, 0);
        int cap = nsm * bpsm;
        int want = (N_EDGES + BS - 1) / BS;          // 1 edge/thread if possible
        int g = cap < want ? cap : want;
        // need g*BS*MAXK >= N_EDGES for full edge coverage
        if (!coop || g <= 0 || g * BS * MAXK < N_EDGES) coop_grid = -1;
        else coop_grid = g;
    }

    if (coop_grid > 0) {
        void* args[4] = { (void*)&demands, (void*)&erow, (void*)&ecol, (void*)&out };
        cudaError_t err = cudaLaunchCooperativeKernel(
            (void*)k_solve, dim3(coop_grid), dim3(BS), args, 0, 0);
        if (err == cudaSuccess) return;
        cudaGetLastError();      // clear; fall through to multi-launch
        coop_grid = -1;
    }

    // ---- fallback: multi-launch path ----
    const int gN = (N_NODES + BS - 1) / BS;
    const int gE = (N_EDGES + BS - 1) / BS;
    k_init<<<gN, BS>>>(demands);
    k_deg<<<gE, BS>>>(erow);
    int cur = 0;
    for (int t = 0; t < 9; t++) {
        int nxt = (cur + 1) % 3, rst = (cur + 2) % 3;
        k_update<<<gE, BS>>>(erow, ecol, cur, nxt, rst);
        cur = nxt;
    }
    k_final<<<gE, BS>>>(erow, out, cur);
}

// round 3
// speedup vs baseline: 1.0357x; 1.0357x over previous
#include <cuda_runtime.h>

// SparseMCFModel: decoder softmax w = seg_softmax(pred_w[edge_row], edge_row)
// has identical logits inside each segment (the logit depends only on the
// segment key), so w[e] == 1/out_degree(edge_row[e]) EXACTLY (exp(0)=1
// bitwise, deg < 2^24 exact in fp32). The GAT/GRU/decoder is dead code w.r.t.
// the output. Remaining computation, in node space:
//   x_1 = relu(demands);  x_{t+1}[n] = d_pos[n] + sum_{col(e)=n} w[e]*x_t[row(e)]
//   flow[e] = w[e] * x_10[row(e)]
//
// One persistent cooperative kernel; edge indices + weights in registers;
// node state hot in L2. R2 lesson: the grid barrier must NOT poll with
// atomics (L2 atomic unit serializes per address). Pollers spin on a plain
// volatile load; only arrival uses one atomicAdd per block.

#define N_NODES 20000
#define N_EDGES 200000
#define BS      256
#define MAXK    4     // max edges per thread (grid sized so 3 suffice)

__device__ float g_dpos[N_NODES];
__device__ float g_x[3][N_NODES];
__device__ int   g_deg[N_NODES];

__device__ unsigned int          g_count = 0;
__device__ volatile unsigned int g_gen   = 0;

__device__ __forceinline__ void grid_sync(unsigned int nblocks) {
    __syncthreads();
    if (threadIdx.x == 0) {
        __threadfence();                       // publish this block's writes
        unsigned int my = g_gen;               // read generation pre-arrival
        unsigned int arrived = atomicAdd(&g_count, 1u);
        if (arrived == nblocks - 1u) {
            g_count = 0u;                      // all arrived; nobody reads count now
            __threadfence();                   // count reset visible before release
            g_gen = my + 1u;                   // release (plain volatile store)
        } else {
            int backoff = 32;
            while (g_gen == my) {              // relaxed volatile poll (no atomic ALU)
                __nanosleep(backoff);
                if (backoff < 256) backoff <<= 1;
            }
        }
        __threadfence();                       // acquire other blocks' writes
    }
    __syncthreads();
}

// ---------------- persistent cooperative solver ----------------
__global__ void __launch_bounds__(BS)
k_solve(const float* __restrict__ demands, const int* __restrict__ row,
        const int* __restrict__ col, float* __restrict__ out) {
    const unsigned int nb = gridDim.x;
    const int tid = blockIdx.x * BS + threadIdx.x;
    const int T   = (int)nb * BS;

    // --- load my edges into registers (once, coalesced per k-slice) ---
    int   r[MAXK], c[MAXK];
    float w[MAXK];
    bool  v[MAXK];
#pragma unroll
    for (int k = 0; k < MAXK; k++) {
        int e = tid + k * T;
        v[k] = (e < N_EDGES);
        r[k] = v[k] ? __ldg(&row[e]) : 0;
        c[k] = v[k] ? __ldg(&col[e]) : 0;
    }

    // --- node init: d_pos, x_1, pre-reset first target, deg=0 ---
    for (int i = tid; i < N_NODES; i += T) {
        float d = __ldg(&demands[i]);
        d = d > 0.0f ? d : 0.0f;
        g_dpos[i] = d;
        g_x[0][i] = d;   // x_1
        g_x[1][i] = d;   // target of first update, pre-reset
        g_deg[i]  = 0;
    }
    grid_sync(nb);

    // --- out-degree ---
#pragma unroll
    for (int k = 0; k < MAXK; k++)
        if (v[k]) atomicAdd(&g_deg[r[k]], 1);
    grid_sync(nb);

    // --- per-edge weight into registers ---
#pragma unroll
    for (int k = 0; k < MAXK; k++)
        w[k] = v[k] ? (1.0f / (float)g_deg[r[k]]) : 0.0f;

    // --- 9 node-state updates: x_1 -> x_10 (3-buffer rotation) ---
    int cur = 0;
#pragma unroll 1
    for (int t = 0; t < 9; t++) {
        int nxt = cur + 1; if (nxt == 3) nxt = 0;
        int rst = nxt + 1; if (rst == 3) rst = 0;
        float xv[MAXK];
#pragma unroll
        for (int k = 0; k < MAXK; k++)          // batch gathers first: MLP
            xv[k] = v[k] ? g_x[cur][r[k]] : 0.0f;
#pragma unroll
        for (int k = 0; k < MAXK; k++)
            if (v[k]) atomicAdd(&g_x[nxt][c[k]], w[k] * xv[k]);
        for (int i = tid; i < N_NODES; i += T)
            g_x[rst][i] = g_dpos[i];            // prep buffer for iter t+2
        grid_sync(nb);
        cur = nxt;
    }

    // --- flow = w * x_10[row] ---
#pragma unroll
    for (int k = 0; k < MAXK; k++)
        if (v[k]) out[tid + k * T] = w[k] * g_x[cur][r[k]];
}

// ---------------- fallback multi-launch path (proven correct) ----------------
__global__ void k_init(const float* __restrict__ demands) {
    int i = blockIdx.x * blockDim.x + threadIdx.x;
    if (i < N_NODES) {
        float d = demands[i];
        d = d > 0.0f ? d : 0.0f;
        g_dpos[i] = d; g_x[0][i] = d; g_x[1][i] = d; g_deg[i] = 0;
    }
}
__global__ void k_deg(const int* __restrict__ row) {
    int e = blockIdx.x * blockDim.x + threadIdx.x;
    if (e < N_EDGES) atomicAdd(&g_deg[row[e]], 1);
}
__global__ void k_update(const int* __restrict__ row, const int* __restrict__ col,
                         int cur, int nxt, int rst) {
    int i = blockIdx.x * blockDim.x + threadIdx.x;
    if (i < N_EDGES) {
        int rr = __ldg(&row[i]);
        float ww = 1.0f / (float)g_deg[rr];
        atomicAdd(&g_x[nxt][__ldg(&col[i])], ww * g_x[cur][rr]);
    }
    if (i < N_NODES) g_x[rst][i] = g_dpos[i];
}
__global__ void k_final(const int* __restrict__ row, float* __restrict__ out, int cur) {
    int e = blockIdx.x * blockDim.x + threadIdx.x;
    if (e < N_EDGES) {
        int rr = __ldg(&row[e]);
        out[e] = (1.0f / (float)g_deg[rr]) * g_x[cur][rr];
    }
}

extern "C" void kernel_launch(void* const* d_in, const int* in_sizes, int n_in,
                              void* d_out, int out_size) {
    const float* demands = (const float*)d_in[1];
    const int*   erow    = (const int*)d_in[2];
    const int*   ecol    = (const int*)d_in[3];
    float*       out     = (float*)d_out;

    // ---- size the cooperative grid: 2 resident blocks per SM ----
    static int coop_grid = -2;   // -2 = not probed; -1 = unsupported
    if (coop_grid == -2) {
        int dev = 0, nsm = 0, coop = 0, bpsm = 0;
        cudaGetDevice(&dev);
        cudaDeviceGetAttribute(&nsm,  cudaDevAttrMultiProcessorCount, dev);
        cudaDeviceGetAttribute(&coop, cudaDevAttrCooperativeLaunch,   dev);
        cudaOccupancyMaxActiveBlocksPerMultiprocessor(&bpsm, k_solve, BS, 0);
        int per_sm = bpsm < 2 ? bpsm : 2;       // cap at 2 blocks/SM
        int g = nsm * per_sm;
        if (!coop || g <= 0 || (long long)g * BS * MAXK < N_EDGES) coop_grid = -1;
        else coop_grid = g;
    }

    if (coop_grid > 0) {
        void* args[4] = { (void*)&demands, (void*)&erow, (void*)&ecol, (void*)&out };
        cudaError_t err = cudaLaunchCooperativeKernel(
            (void*)k_solve, dim3(coop_grid), dim3(BS), args, 0, 0);
        if (err == cudaSuccess) return;
        cudaGetLastError();
        coop_grid = -1;          // fall through permanently
    }

    // ---- fallback: multi-launch path ----
    const int gN = (N_NODES + BS - 1) / BS;
    const int gE = (N_EDGES + BS - 1) / BS;
    k_init<<<gN, BS>>>(demands);
    k_deg<<<gE, BS>>>(erow);
    int cur = 0;
    for (int t = 0; t < 9; t++) {
        int nxt = (cur + 1) % 3, rst = (cur + 2) % 3;
        k_update<<<gE, BS>>>(erow, ecol, cur, nxt, rst);
        cur = nxt;
    }
    k_final<<<gE, BS>>>(erow, out, cur);
}